// round 16
// baseline (speedup 1.0000x reference)
#include <cuda_runtime.h>
#include <cuda_bf16.h>

// ---------------------------------------------------------------------------
// GeoConvNet3DMeshSeg — full mesh U-Net forward.
// R16: tensor conv generalized (template over CA/CB/Cout + split-K) and used
//      for d1, d2, d3 (all decoder layers: no downstream top-k -> no tie risk).
//      Weights pre-converted to tf32 hi/lo at stage time (fragment order in
//      smem) — removes 64 cvt instrs/unit/thread from the MMA inner loop.
//      Encoder layers keep the proven R13 scalar path (they feed pool ties).
// NOTE: nb input is INT32 (jax downcasts int64 -> int32 with x64 disabled).
// ---------------------------------------------------------------------------

#define CDIV(a, b) (((a) + (b) - 1) / (b))

static const int EN = 200000;
static const int T1 = 1500, T2 = 750, T3 = 375;

// ---------------- float arena ----------------
static const long long F_E1   = 0;                              // EN*64
static const long long F_D1   = F_E1   + (long long)EN * 64;    // EN*64
static const long long F_SC   = F_D1   + (long long)EN * 64;    // EN
static const long long F_E1P  = F_SC   + EN;                    // T1*64
static const long long F_E2   = F_E1P  + (long long)T1 * 64;    // T1*128
static const long long F_E2P  = F_E2   + (long long)T1 * 128;   // T2*128
static const long long F_E3   = F_E2P  + (long long)T2 * 128;   // T2*256
static const long long F_E3P  = F_E3   + (long long)T2 * 256;   // T3*256
static const long long F_E4   = F_E3P  + (long long)T3 * 256;   // T3*512
static const long long F_D3   = F_E4   + (long long)T3 * 512;   // T2*256
static const long long F_D2   = F_D3   + (long long)T2 * 256;   // T1*128
static const long long F_HP   = F_D2   + (long long)T1 * 128;   // split-K partials
static const long long F_PB   = F_HP   + 2600000;               // BN partials
static const long long F_SS   = F_PB   + 140000;                // BN scale/shift
static const long long F_TOT  = F_SS   + 2048;

// ---------------- int arena ----------------
static const long long I_NB0  = 0;                              // EN*4
static const long long I_NB1  = I_NB0 + (long long)EN * 4;      // T1*4
static const long long I_NB2  = I_NB1 + T1 * 4;                 // T2*4
static const long long I_NB3  = I_NB2 + T2 * 4;                 // T3*4
static const long long I_K1   = I_NB3 + T3 * 4;                 // T1
static const long long I_K2   = I_K1 + T1;                      // T2
static const long long I_K3   = I_K2 + T2;                      // T3
static const long long I_RM1  = I_K3 + T3;                      // EN
static const long long I_NN1  = I_RM1 + EN;                     // EN
static const long long I_NN2  = I_NN1 + EN;                     // T1
static const long long I_NN3  = I_NN2 + T1;                     // T2
static const long long I_FEQ  = I_NN3 + T2;                     // EN
static const long long I_EQR  = I_FEQ + EN;                     // EN
static const long long I_FKP  = I_EQR + EN;                     // EN
static const long long I_POS  = I_FKP + EN;                     // EN
static const long long I_BSUM = I_POS + EN;                     // 1024
static const long long I_H1   = I_BSUM + 1024;                  // 16384
static const long long I_H2   = I_H1 + 16384;                   // 262144
static const long long I_SEL  = I_H2 + 262144;                  // 8
static const long long I_TOT  = I_SEL + 8;

__device__ __align__(16) float g_f[F_TOT];
__device__ __align__(16) int   g_i[I_TOT];

// ---------------------------------------------------------------------------
// misc small kernels
// ---------------------------------------------------------------------------
__global__ void zero_hists_kernel(unsigned* h1, unsigned* h2) {
    int n = 16384 + 262144;
    for (int i = blockIdx.x * blockDim.x + threadIdx.x; i < n; i += gridDim.x * blockDim.x) {
        if (i < 16384) h1[i] = 0u; else h2[i - 16384] = 0u;
    }
}

__global__ void nbconv_kernel(const int* __restrict__ nb32, int n4, int E,
                              int* __restrict__ out) {
    int i = blockIdx.x * blockDim.x + threadIdx.x;
    if (i >= n4) return;
    int v = nb32[i];
    if (v < 0) v = 0;
    if (v >= E) v = E - 1;
    out[i] = v;
}

// ---------------------------------------------------------------------------
// Scalar double-buffered conv (R13, proven) — encoder layers (feed pool ties).
// ---------------------------------------------------------------------------
#define MM4(A0, A1, A2, A3, rv, cv)                                          \
    A0.x = fmaf(rv.x, cv.x, A0.x); A0.y = fmaf(rv.x, cv.y, A0.y);            \
    A0.z = fmaf(rv.x, cv.z, A0.z); A0.w = fmaf(rv.x, cv.w, A0.w);            \
    A1.x = fmaf(rv.y, cv.x, A1.x); A1.y = fmaf(rv.y, cv.y, A1.y);            \
    A1.z = fmaf(rv.y, cv.z, A1.z); A1.w = fmaf(rv.y, cv.w, A1.w);            \
    A2.x = fmaf(rv.z, cv.x, A2.x); A2.y = fmaf(rv.z, cv.y, A2.y);            \
    A2.z = fmaf(rv.z, cv.z, A2.z); A2.w = fmaf(rv.z, cv.w, A2.w);            \
    A3.x = fmaf(rv.w, cv.x, A3.x); A3.y = fmaf(rv.w, cv.y, A3.y);            \
    A3.z = fmaf(rv.w, cv.z, A3.z); A3.w = fmaf(rv.w, cv.w, A3.w);

template <int KCH>
__global__ __launch_bounds__(256) void conv_kernel(
    const float* __restrict__ A, int CA,
    const int* __restrict__ nb, int R, int Cout, const float* __restrict__ W,
    float* __restrict__ Hout, int splits)
{
    const int C = CA;
    const int IT = KCH / 4;
    const int LSH = (KCH == 32) ? 5 : ((KCH == 16) ? 4 : 3);
    const int SFSZ = 2 * KCH * 68;
    const int SWSZ = 2 * KCH * 64;
    __shared__ int   SN[256];
    __shared__ float SF[2 * 2 * KCH * 68];
    __shared__ float SW[2 * 2 * KCH * 64];

    const int tid  = threadIdx.x;
    const int row0 = blockIdx.x * 64;
    const int col0 = blockIdx.y * 64;
    const int zid  = blockIdx.z;
    const int tr = tid >> 4, tc = tid & 15;
    const int nchunk = (C + KCH - 1) / KCH;
    const int totalu = 3 * nchunk;

    float4 a00 = {0,0,0,0}, a01 = a00, a02 = a00, a03 = a00;
    float fa[IT], fb[IT], wa[IT], wb[IT];

    {
        int gi = row0 + (tid >> 2);
        SN[tid] = (gi < R) ? nb[gi * 4 + (tid & 3)] : 0;
    }
    __syncthreads();

    auto prefetch = [&](int u) {
        int st = u / nchunk, ck = u - st * nchunk;
        int k0 = ck * KCH;
        #pragma unroll
        for (int it = 0; it < IT; it++) {
            int e = tid + it * 256;
            int kk = e & (KCH - 1), row = e >> LSH;
            int ch = k0 + kk;
            int gi = row0 + row;
            bool ok = (gi < R) && (ch < C);
            if (st == 0) {
                float v = ok ? A[(size_t)gi * CA + ch] : 0.f;
                fa[it] = v; fb[it] = v;
            } else {
                float a = 0.f, b = 0.f;
                if (ok) {
                    int j0 = row * 4 + (st - 1) * 2;
                    a = A[(size_t)SN[j0]     * CA + ch];
                    b = A[(size_t)SN[j0 + 1] * CA + ch];
                }
                fa[it] = a; fb[it] = b;
            }
        }
        int part0 = (st == 0) ? 0 : (2 * st - 1);
        #pragma unroll
        for (int it = 0; it < IT; it++) {
            int e = tid + it * 256;
            int cc = e & 63, kk = e >> 6;
            int ch = k0 + kk;
            bool okc = (ch < C);
            wa[it] = okc ? W[(size_t)(part0 * C + ch) * Cout + col0 + cc] : 0.f;
            wb[it] = (st && okc) ? W[(size_t)((part0 + 1) * C + ch) * Cout + col0 + cc] : 0.f;
        }
    };

    auto stage = [&](int u, int p) {
        int st = u / nchunk;
        float* SFb = SF + p * SFSZ;
        float* SWb = SW + p * SWSZ;
        #pragma unroll
        for (int it = 0; it < IT; it++) {
            int e = tid + it * 256;
            int kk = e & (KCH - 1), row = e >> LSH;
            if (st == 0) {
                SFb[kk * 68 + row] = fa[it];
            } else {
                SFb[kk * 68 + row]            = fminf(fa[it], fb[it]);
                SFb[KCH * 68 + kk * 68 + row] = fmaxf(fa[it], fb[it]);
            }
        }
        #pragma unroll
        for (int it = 0; it < IT; it++) {
            int e = tid + it * 256;
            int cc = e & 63, kk = e >> 6;
            SWb[kk * 64 + cc] = wa[it];
            if (st) SWb[KCH * 64 + kk * 64 + cc] = wb[it];
        }
    };

    int u = zid;
    int p = 0;
    if (u < totalu) prefetch(u);
    while (u < totalu) {
        int unext = u + splits;
        stage(u, p);
        if (unext < totalu) prefetch(unext);
        __syncthreads();
        int st = u / nchunk;
        const float* SFb = SF + p * SFSZ;
        const float* SWb = SW + p * SWSZ;
        if (st == 0) {
            #pragma unroll
            for (int kk = 0; kk < KCH; kk++) {
                float4 rv = *(const float4*)&SFb[kk * 68 + tr * 4];
                float4 cv = *(const float4*)&SWb[kk * 64 + tc * 4];
                MM4(a00, a01, a02, a03, rv, cv)
            }
        } else {
            #pragma unroll
            for (int kk = 0; kk < KCH; kk++) {
                float4 rv = *(const float4*)&SFb[kk * 68 + tr * 4];
                float4 cv = *(const float4*)&SWb[kk * 64 + tc * 4];
                MM4(a00, a01, a02, a03, rv, cv)
                float4 rv2 = *(const float4*)&SFb[KCH * 68 + kk * 68 + tr * 4];
                float4 cv2 = *(const float4*)&SWb[KCH * 64 + kk * 64 + tc * 4];
                MM4(a00, a01, a02, a03, rv2, cv2)
            }
        }
        u = unext;
        p ^= 1;
    }

    float* O = Hout + (size_t)zid * R * Cout;
    float4 rows[4] = {a00, a01, a02, a03};
    #pragma unroll
    for (int qr = 0; qr < 4; qr++) {
        int gi = row0 + tr * 4 + qr;
        if (gi < R)
            *(float4*)&O[(size_t)gi * Cout + col0 + tc * 4] = rows[qr];
    }
}

// ---------------------------------------------------------------------------
// Tensor conv (decoder layers): split-TF32 mma.sync.m16n8k8, 3 passes.
// Template over CA (coarse feats via mapA), CB (skip feats), TCOUT.
// Block 128 rows x 64 cols (col0 = by*64), 8 warps, warp = 16 rows.
// Weights pre-converted to tf32 hi/lo at STAGE time, fragment order ->
// inner loop is pure LDS + MMA (plus 8 A-cvts per plane).
// Split-K over gridDim.z (units dealt round-robin); partials reduced after.
// ---------------------------------------------------------------------------
__device__ __forceinline__ unsigned tf32cvt(float x) {
    unsigned r; asm("cvt.rna.tf32.f32 %0, %1;" : "=r"(r) : "f"(x)); return r;
}
#define MMA_TF32(c0, c1, c2, c3, a0, a1, a2, a3, b0, b1)                      \
    asm("mma.sync.aligned.m16n8k8.row.col.f32.tf32.tf32.f32 "                 \
        "{%0,%1,%2,%3}, {%4,%5,%6,%7}, {%8,%9}, {%0,%1,%2,%3};"               \
        : "+f"(c0), "+f"(c1), "+f"(c2), "+f"(c3)                              \
        : "r"(a0), "r"(a1), "r"(a2), "r"(a3), "r"(b0), "r"(b1))

template <int TCA, int TCB, int TCOUT>
__global__ __launch_bounds__(256) void conv_tensor_kernel(
    const float* __restrict__ A, const int* __restrict__ mapA,
    const float* __restrict__ B,
    const int* __restrict__ nb, int R, const float* __restrict__ W,
    float* __restrict__ Hout, int splits)
{
    const int C = TCA + TCB;
    const int KCH = 8, nchunk = C / KCH, totalu = 3 * nchunk;
    const int SFSZ = 2 * KCH * 132;
    __shared__ int      SN[512];
    __shared__ int      SNA[512];
    __shared__ int      SMA[128];
    __shared__ float    SF[2 * 2 * KCH * 132];
    __shared__ unsigned SWhi[2 * 2 * 512];   // [buf][plane][fragment slot]
    __shared__ unsigned SWlo[2 * 2 * 512];

    const int tid  = threadIdx.x;
    const int row0 = blockIdx.x * 128;
    const int col0 = blockIdx.y * 64;
    const int zid  = blockIdx.z;
    const int wid = tid >> 5, lane = tid & 31;

    float acc[8][4];
    #pragma unroll
    for (int n = 0; n < 8; n++) { acc[n][0] = acc[n][1] = acc[n][2] = acc[n][3] = 0.f; }

    float fa[4], fb[4], wa[2], wb[2];

    #pragma unroll
    for (int it = 0; it < 2; it++) {
        int e = tid + it * 256;                 // 128 rows x 4 nbrs
        int gi = row0 + (e >> 2);
        int nbv = (gi < R) ? nb[gi * 4 + (e & 3)] : 0;
        SN[e] = nbv;
        SNA[e] = mapA[nbv];
    }
    if (tid < 128) {
        int g2 = row0 + tid;
        SMA[tid] = mapA[(g2 < R) ? g2 : 0];
    }
    __syncthreads();

    auto prefetch = [&](int u) {
        int st = u / nchunk, ck = u - st * nchunk;
        int k0 = ck * KCH;
        #pragma unroll
        for (int it = 0; it < 4; it++) {
            int e = tid + it * 256;             // 128 rows x 8 kk
            int kk = e & 7, row = e >> 3;
            int ch = k0 + kk;
            int gi = row0 + row;
            bool ok = (gi < R);
            if (st == 0) {
                float v = 0.f;
                if (ok) v = (ch < TCA) ? A[(size_t)SMA[row] * TCA + ch]
                                       : B[(size_t)gi * TCB + (ch - TCA)];
                fa[it] = v; fb[it] = v;
            } else {
                float a = 0.f, b = 0.f;
                if (ok) {
                    int j0 = row * 4 + (st - 1) * 2;
                    if (ch < TCA) {
                        a = A[(size_t)SNA[j0]     * TCA + ch];
                        b = A[(size_t)SNA[j0 + 1] * TCA + ch];
                    } else {
                        a = B[(size_t)SN[j0]     * TCB + (ch - TCA)];
                        b = B[(size_t)SN[j0 + 1] * TCB + (ch - TCA)];
                    }
                }
                fa[it] = a; fb[it] = b;
            }
        }
        int part0 = (st == 0) ? 0 : (2 * st - 1);
        #pragma unroll
        for (int it = 0; it < 2; it++) {
            int e = tid + it * 256;             // 8 kk x 64 cc
            int cc = e & 63, kk = e >> 6;
            int ch = k0 + kk;
            wa[it] = W[(size_t)(part0 * C + ch) * TCOUT + col0 + cc];
            wb[it] = st ? W[(size_t)((part0 + 1) * C + ch) * TCOUT + col0 + cc] : 0.f;
        }
    };

    auto stage = [&](int u, int p) {
        int st = u / nchunk;
        float* SFb = SF + p * SFSZ;
        unsigned* SHb = SWhi + p * 1024;
        unsigned* SLb = SWlo + p * 1024;
        #pragma unroll
        for (int it = 0; it < 4; it++) {
            int e = tid + it * 256;
            int kk = e & 7, row = e >> 3;
            if (st == 0) {
                SFb[kk * 132 + row] = fa[it];
            } else {
                SFb[kk * 132 + row]             = fminf(fa[it], fb[it]);
                SFb[KCH * 132 + kk * 132 + row] = fmaxf(fa[it], fb[it]);
            }
        }
        #pragma unroll
        for (int it = 0; it < 2; it++) {
            int e = tid + it * 256;
            int cc = e & 63, kk = e >> 6;
            int n = cc >> 3, r = cc & 7;
            int slot = n * 64 + (r * 4 + (kk & 3)) * 2 + (kk >> 2);
            unsigned hi0 = tf32cvt(wa[it]);
            SHb[slot] = hi0;
            SLb[slot] = tf32cvt(wa[it] - __uint_as_float(hi0));
            if (st) {
                unsigned hi1 = tf32cvt(wb[it]);
                SHb[512 + slot] = hi1;
                SLb[512 + slot] = tf32cvt(wb[it] - __uint_as_float(hi1));
            }
        }
    };

    int u = zid, p = 0;
    if (u < totalu) prefetch(u);
    while (u < totalu) {
        int unext = u + splits;
        stage(u, p);
        if (unext < totalu) prefetch(unext);
        __syncthreads();
        int st = u / nchunk;
        int planes = st ? 2 : 1;
        const float* SFb = SF + p * SFSZ;
        const unsigned* SHb = SWhi + p * 1024;
        const unsigned* SLb = SWlo + p * 1024;
        #pragma unroll
        for (int plane = 0; plane < 2; plane++) {
            if (plane >= planes) break;
            const float* F = SFb + plane * KCH * 132;
            const unsigned* Whi = SHb + plane * 512;
            const unsigned* Wlo = SLb + plane * 512;
            int r0 = (wid << 4) + (lane >> 2);
            int kq = lane & 3;
            float a0f = F[kq * 132 + r0];
            float a1f = F[kq * 132 + r0 + 8];
            float a2f = F[(kq + 4) * 132 + r0];
            float a3f = F[(kq + 4) * 132 + r0 + 8];
            unsigned ah0 = tf32cvt(a0f), ah1 = tf32cvt(a1f);
            unsigned ah2 = tf32cvt(a2f), ah3 = tf32cvt(a3f);
            unsigned al0 = tf32cvt(a0f - __uint_as_float(ah0));
            unsigned al1 = tf32cvt(a1f - __uint_as_float(ah1));
            unsigned al2 = tf32cvt(a2f - __uint_as_float(ah2));
            unsigned al3 = tf32cvt(a3f - __uint_as_float(ah3));
            #pragma unroll
            for (int n = 0; n < 8; n++) {
                uint2 bh = *(const uint2*)&Whi[n * 64 + lane * 2];
                uint2 bl = *(const uint2*)&Wlo[n * 64 + lane * 2];
                MMA_TF32(acc[n][0], acc[n][1], acc[n][2], acc[n][3],
                         ah0, ah1, ah2, ah3, bh.x, bh.y);
                MMA_TF32(acc[n][0], acc[n][1], acc[n][2], acc[n][3],
                         ah0, ah1, ah2, ah3, bl.x, bl.y);
                MMA_TF32(acc[n][0], acc[n][1], acc[n][2], acc[n][3],
                         al0, al1, al2, al3, bh.x, bh.y);
            }
        }
        u = unext;
        p ^= 1;
    }

    // epilogue: fragment layout -> per-split partial output
    float* O = Hout + (size_t)zid * R * TCOUT;
    int rbase = row0 + (wid << 4) + (lane >> 2);
    #pragma unroll
    for (int n = 0; n < 8; n++) {
        int col = col0 + n * 8 + (lane & 3) * 2;
        if (rbase < R) {
            float2 v = {acc[n][0], acc[n][1]};
            *(float2*)&O[(size_t)rbase * TCOUT + col] = v;
        }
        if (rbase + 8 < R) {
            float2 v = {acc[n][2], acc[n][3]};
            *(float2*)&O[(size_t)(rbase + 8) * TCOUT + col] = v;
        }
    }
}

__global__ void reduce_split_kernel(float* __restrict__ H, const float* __restrict__ part,
                                    long long n, int splits) {
    long long i = (long long)blockIdx.x * blockDim.x + threadIdx.x;
    long long stride = (long long)gridDim.x * blockDim.x;
    for (; i < n; i += stride) {
        float s = 0.f;
        for (int z = 0; z < splits; z++) s += part[(long long)z * n + i];
        H[i] = s;
    }
}

// ---------------------------------------------------------------------------
// BatchNorm (training stats) + ReLU : deterministic two-level reduction
// ---------------------------------------------------------------------------
__global__ void bn_reduce_kernel(const float* __restrict__ H, int R, int Cout,
                                 float* __restrict__ partial) {
    int b = blockIdx.x;
    int r0 = b * 256;
    int rend = min(R, r0 + 256);
    for (int c = threadIdx.x; c < Cout; c += 256) {
        float s = 0.f, s2 = 0.f;
        for (int r = r0; r < rend; r++) {
            float v = H[(size_t)r * Cout + c];
            s += v; s2 += v * v;
        }
        partial[((size_t)b * Cout + c) * 2]     = s;
        partial[((size_t)b * Cout + c) * 2 + 1] = s2;
    }
}

__global__ void bn_finalize_kernel(const float* __restrict__ partial, int nblk, int Cout,
                                   int R, const float* __restrict__ g,
                                   const float* __restrict__ bta, float* __restrict__ ss) {
    __shared__ float s1[256], s2s[256];
    int c = blockIdx.x;
    float s = 0.f, s2 = 0.f;
    for (int b = threadIdx.x; b < nblk; b += 256) {
        s  += partial[((size_t)b * Cout + c) * 2];
        s2 += partial[((size_t)b * Cout + c) * 2 + 1];
    }
    s1[threadIdx.x] = s; s2s[threadIdx.x] = s2;
    __syncthreads();
    for (int off = 128; off > 0; off >>= 1) {
        if (threadIdx.x < off) {
            s1[threadIdx.x] += s1[threadIdx.x + off];
            s2s[threadIdx.x] += s2s[threadIdx.x + off];
        }
        __syncthreads();
    }
    if (threadIdx.x == 0) {
        float mu  = s1[0] / (float)R;
        float var = s2s[0] / (float)R - mu * mu;
        if (var < 0.f) var = 0.f;
        float sc = rsqrtf(var + 1e-5f) * g[c];
        ss[c * 2]     = sc;
        ss[c * 2 + 1] = bta[c] - mu * sc;
    }
}

__global__ void bn_apply_kernel(float* __restrict__ H, long long n, int Cmask,
                                const float* __restrict__ ss) {
    long long i = (long long)blockIdx.x * blockDim.x + threadIdx.x;
    long long stride = (long long)gridDim.x * blockDim.x;
    for (; i < n; i += stride) {
        int c = (int)(i & Cmask);
        float h = H[i] * ss[c * 2] + ss[c * 2 + 1];
        H[i] = fmaxf(h, 0.f);
    }
}

// Fused: BN+ReLU in place on e1 (Cout=64) AND row L2-norm score.
__global__ __launch_bounds__(256) void bn_apply_score_kernel(float* __restrict__ H, int R,
                                                             const float* __restrict__ ss,
                                                             float* __restrict__ sc) {
    __shared__ float s2[128];
    if (threadIdx.x < 128) s2[threadIdx.x] = ss[threadIdx.x];
    __syncthreads();
    int r = blockIdx.x * 256 + threadIdx.x;
    if (r >= R) return;
    float4* row = (float4*)(H + (size_t)r * 64);
    float acc = 0.f;
    #pragma unroll
    for (int q = 0; q < 16; q++) {
        float4 v = row[q];
        int c = q * 4;
        v.x = fmaxf(v.x * s2[(c + 0) * 2] + s2[(c + 0) * 2 + 1], 0.f);
        v.y = fmaxf(v.y * s2[(c + 1) * 2] + s2[(c + 1) * 2 + 1], 0.f);
        v.z = fmaxf(v.z * s2[(c + 2) * 2] + s2[(c + 2) * 2 + 1], 0.f);
        v.w = fmaxf(v.w * s2[(c + 3) * 2] + s2[(c + 3) * 2 + 1], 0.f);
        acc += v.x * v.x + v.y * v.y + v.z * v.z + v.w * v.w;
        row[q] = v;
    }
    sc[r] = sqrtf(acc);
}

// Fused: BN+ReLU on d1 (read-only) + head GEMV -> out[R,4].
__global__ __launch_bounds__(256) void bn_apply_head_kernel(const float* __restrict__ H, int R,
                                                            const float* __restrict__ ss,
                                                            const float* __restrict__ Wh,
                                                            const float* __restrict__ bh,
                                                            float* __restrict__ out) {
    __shared__ float s2[128];
    __shared__ float sw[256];
    __shared__ float sb[4];
    if (threadIdx.x < 128) s2[threadIdx.x] = ss[threadIdx.x];
    sw[threadIdx.x] = Wh[threadIdx.x];
    if (threadIdx.x < 4) sb[threadIdx.x] = bh[threadIdx.x];
    __syncthreads();
    int r = blockIdx.x * 256 + threadIdx.x;
    if (r >= R) return;
    const float4* row = (const float4*)(H + (size_t)r * 64);
    float a0 = sb[0], a1 = sb[1], a2 = sb[2], a3 = sb[3];
    #pragma unroll
    for (int q = 0; q < 16; q++) {
        float4 v = row[q];
        int c = q * 4;
        v.x = fmaxf(v.x * s2[(c + 0) * 2] + s2[(c + 0) * 2 + 1], 0.f);
        v.y = fmaxf(v.y * s2[(c + 1) * 2] + s2[(c + 1) * 2 + 1], 0.f);
        v.z = fmaxf(v.z * s2[(c + 2) * 2] + s2[(c + 2) * 2 + 1], 0.f);
        v.w = fmaxf(v.w * s2[(c + 3) * 2] + s2[(c + 3) * 2 + 1], 0.f);
        a0 += v.x * sw[(c + 0) * 4 + 0] + v.y * sw[(c + 1) * 4 + 0] + v.z * sw[(c + 2) * 4 + 0] + v.w * sw[(c + 3) * 4 + 0];
        a1 += v.x * sw[(c + 0) * 4 + 1] + v.y * sw[(c + 1) * 4 + 1] + v.z * sw[(c + 2) * 4 + 1] + v.w * sw[(c + 3) * 4 + 1];
        a2 += v.x * sw[(c + 0) * 4 + 2] + v.y * sw[(c + 1) * 4 + 2] + v.z * sw[(c + 2) * 4 + 2] + v.w * sw[(c + 3) * 4 + 2];
        a3 += v.x * sw[(c + 0) * 4 + 3] + v.y * sw[(c + 1) * 4 + 3] + v.z * sw[(c + 2) * 4 + 3] + v.w * sw[(c + 3) * 4 + 3];
    }
    float4 o = {a0, a1, a2, a3};
    *(float4*)&out[(size_t)r * 4] = o;
}

// ---------------------------------------------------------------------------
// Pool 1 (200000 -> 1500): exact radix select on float bits + scan compaction
// ---------------------------------------------------------------------------
__global__ void hist1_kernel(const float* __restrict__ sc, int n, unsigned* __restrict__ h1) {
    int i = blockIdx.x * blockDim.x + threadIdx.x;
    int stride = gridDim.x * blockDim.x;
    for (; i < n; i += stride) {
        unsigned u = __float_as_uint(sc[i]);
        atomicAdd(&h1[u >> 18], 1u);
    }
}

__global__ __launch_bounds__(1024) void pick1_kernel(const unsigned* __restrict__ h1,
                                                     int k, int* __restrict__ sel) {
    __shared__ unsigned cs[1024];
    int t = threadIdx.x;
    unsigned s = 0;
    for (int j = 0; j < 16; j++) s += h1[t * 16 + j];
    cs[t] = s;
    __syncthreads();
    if (t == 0) {
        unsigned cum = 0;
        int chunk = 0;
        for (int q = 1023; q >= 0; q--) {
            if (cum + cs[q] >= (unsigned)k) { chunk = q; break; }
            cum += cs[q];
        }
        int bin = chunk * 16;
        for (int j = 15; j >= 0; j--) {
            unsigned hv = h1[chunk * 16 + j];
            if (cum + hv >= (unsigned)k) { bin = chunk * 16 + j; break; }
            cum += hv;
        }
        sel[0] = bin;
        sel[1] = (int)cum;
    }
}

__global__ void hist2_kernel(const float* __restrict__ sc, int n,
                             unsigned* __restrict__ h2, const int* __restrict__ sel) {
    unsigned bin = (unsigned)sel[0];
    int i = blockIdx.x * blockDim.x + threadIdx.x;
    int stride = gridDim.x * blockDim.x;
    for (; i < n; i += stride) {
        unsigned u = __float_as_uint(sc[i]);
        if ((u >> 18) == bin) atomicAdd(&h2[u & 0x3FFFFu], 1u);
    }
}

__global__ __launch_bounds__(1024) void pick2_kernel(const unsigned* __restrict__ h2,
                                                     int k, int* __restrict__ sel) {
    __shared__ unsigned cs[1024];
    int t = threadIdx.x;
    unsigned s = 0;
    for (int j = 0; j < 256; j++) s += h2[t * 256 + j];
    cs[t] = s;
    __syncthreads();
    if (t == 0) {
        unsigned cum = (unsigned)sel[1];
        int chunk = 0;
        for (int q = 1023; q >= 0; q--) {
            if (cum + cs[q] >= (unsigned)k) { chunk = q; break; }
            cum += cs[q];
        }
        int L = chunk * 256;
        for (int j = 255; j >= 0; j--) {
            unsigned hv = h2[chunk * 256 + j];
            if (cum + hv >= (unsigned)k) { L = chunk * 256 + j; break; }
            cum += hv;
        }
        sel[2] = (int)(((unsigned)sel[0] << 18) | (unsigned)L);
        sel[3] = k - (int)cum;
    }
}

__global__ void flags_eq_kernel(const float* __restrict__ sc, int n,
                                const int* __restrict__ sel, int* __restrict__ f) {
    unsigned thr = (unsigned)sel[2];
    int i = blockIdx.x * blockDim.x + threadIdx.x;
    if (i < n) f[i] = (__float_as_uint(sc[i]) == thr) ? 1 : 0;
}

__global__ void flags_keep_kernel(const float* __restrict__ sc, int n,
                                  const int* __restrict__ sel,
                                  const int* __restrict__ eqrank, int* __restrict__ f) {
    unsigned thr = (unsigned)sel[2];
    int need = sel[3];
    int i = blockIdx.x * blockDim.x + threadIdx.x;
    if (i < n) {
        unsigned u = __float_as_uint(sc[i]);
        f[i] = (u > thr || (u == thr && eqrank[i] < need)) ? 1 : 0;
    }
}

__global__ __launch_bounds__(256) void scan_blk_kernel(const int* __restrict__ in,
                                                       int* __restrict__ out,
                                                       int* __restrict__ bsum, int n) {
    __shared__ int s[256];
    int blk = blockIdx.x;
    int base = blk * 1024;
    int v[4], tsum = 0;
    #pragma unroll
    for (int q = 0; q < 4; q++) {
        int idx = base + threadIdx.x * 4 + q;
        v[q] = (idx < n) ? in[idx] : 0;
        tsum += v[q];
    }
    s[threadIdx.x] = tsum;
    __syncthreads();
    for (int off = 1; off < 256; off <<= 1) {
        int t = (threadIdx.x >= off) ? s[threadIdx.x - off] : 0;
        __syncthreads();
        s[threadIdx.x] += t;
        __syncthreads();
    }
    int run = s[threadIdx.x] - tsum;
    if (threadIdx.x == 255) bsum[blk] = s[255];
    #pragma unroll
    for (int q = 0; q < 4; q++) {
        int idx = base + threadIdx.x * 4 + q;
        if (idx < n) out[idx] = run;
        run += v[q];
    }
}

__global__ void scan_top_kernel(int* __restrict__ bsum, int nb) {
    __shared__ int s[1024];
    for (int i = threadIdx.x; i < nb; i += blockDim.x) s[i] = bsum[i];
    __syncthreads();
    if (threadIdx.x == 0) {
        int run = 0;
        for (int i = 0; i < nb; i++) { int v = s[i]; s[i] = run; run += v; }
    }
    __syncthreads();
    for (int i = threadIdx.x; i < nb; i += blockDim.x) bsum[i] = s[i];
}

__global__ void scan_add_kernel(int* __restrict__ out, const int* __restrict__ bsum, int n) {
    int i = blockIdx.x * blockDim.x + threadIdx.x;
    if (i < n) out[i] += bsum[i >> 10];
}

__global__ void scatter_kernel(const int* __restrict__ fkp, const int* __restrict__ pos,
                               int n, int* __restrict__ keep, int* __restrict__ remap) {
    int i = blockIdx.x * blockDim.x + threadIdx.x;
    if (i >= n) return;
    if (fkp[i]) { int p = pos[i]; keep[p] = i; remap[i] = p; }
    else remap[i] = -1;
}

__global__ void gather_pool1_kernel(const float* __restrict__ X, const int* __restrict__ nb0,
                                    const int* __restrict__ keep, const int* __restrict__ remap,
                                    int k, int C, float* __restrict__ Xp, int* __restrict__ nbp) {
    int i = blockIdx.x * blockDim.x + threadIdx.x;
    int stride = gridDim.x * blockDim.x;
    for (int e = i; e < k * C; e += stride) {
        int j = e / C, c = e - j * C;
        Xp[e] = X[(size_t)keep[j] * C + c];
    }
    for (int e = i; e < k * 4; e += stride) {
        int j = e >> 2, t = e & 3;
        int v = remap[nb0[keep[j] * 4 + t]];
        nbp[e] = (v < 0) ? j : v;
    }
}

// ---------------------------------------------------------------------------
// Small pools (single block, O(n^2) exact rank)
// ---------------------------------------------------------------------------
__global__ __launch_bounds__(1024) void pool_small_kernel(
    const float* __restrict__ X, const int* __restrict__ nbin,
    int R, int C, int k,
    float* __restrict__ Xp, int* __restrict__ nbp, int* __restrict__ keep)
{
    __shared__ float sSc[1536];
    __shared__ int   sFlag[1536];
    __shared__ int   sPos[1536];
    int t = threadIdx.x;
    for (int i = t; i < R; i += 1024) {
        const float* row = X + (size_t)i * C;
        float s = 0.f;
        for (int c = 0; c < C; c++) { float v = row[c]; s += v * v; }
        sSc[i] = sqrtf(s);
    }
    __syncthreads();
    for (int i = t; i < R; i += 1024) {
        float mine = sSc[i];
        int cnt = 0;
        for (int j = 0; j < R; j++) {
            float sj = sSc[j];
            cnt += (sj > mine || (sj == mine && j < i)) ? 1 : 0;
        }
        sFlag[i] = (cnt < k) ? 1 : 0;
    }
    __syncthreads();
    for (int i = t; i < R; i += 1024) {
        int p = 0;
        for (int j = 0; j < i; j++) p += sFlag[j];
        sPos[i] = p;
    }
    __syncthreads();
    for (int i = t; i < R; i += 1024)
        if (sFlag[i]) keep[sPos[i]] = i;
    for (long long e = t; e < (long long)R * C; e += 1024) {
        int i = (int)(e / C), c = (int)(e - (long long)i * C);
        if (sFlag[i]) Xp[(size_t)sPos[i] * C + c] = X[e];
    }
    for (int e = t; e < R * 4; e += 1024) {
        int i = e >> 2, tt = e & 3;
        if (sFlag[i]) {
            int nbv = nbin[e];
            int v = sFlag[nbv] ? sPos[nbv] : -1;
            nbp[sPos[i] * 4 + tt] = (v < 0) ? sPos[i] : v;
        }
    }
}

// ---------------------------------------------------------------------------
// Unpool: nearest kept index (searchsorted-left + tie to lower)
// ---------------------------------------------------------------------------
__global__ void nn_kernel(const int* __restrict__ keep, int K, int Ef, int* __restrict__ nn) {
    int i = blockIdx.x * blockDim.x + threadIdx.x;
    if (i >= Ef) return;
    int lo = 0, hi = K;
    while (lo < hi) {
        int m = (lo + hi) >> 1;
        if (keep[m] < i) lo = m + 1; else hi = m;
    }
    int left = lo - 1; if (left < 0) left = 0; if (left > K - 1) left = K - 1;
    int right = lo;    if (right > K - 1) right = K - 1;
    int dl = abs(i - keep[left]);
    int dr = abs(i - keep[right]);
    nn[i] = (dl <= dr) ? left : right;
}

// ---------------------------------------------------------------------------
// host-side layer drivers
// ---------------------------------------------------------------------------
static void run_conv(const float* A, int CA,
                     const int* nb, int R, int Cout, const float* W,
                     const float* g, const float* bta,
                     float* H, float* HP, float* PB, float* SS, int splits,
                     bool doApply) {
    dim3 grid(CDIV(R, 64), Cout / 64, splits);
    float* target = (splits == 1) ? H : HP;
    if (CA <= 8)
        conv_kernel<8><<<grid, 256>>>(A, CA, nb, R, Cout, W, target, splits);
    else
        conv_kernel<16><<<grid, 256>>>(A, CA, nb, R, Cout, W, target, splits);
    long long n = (long long)R * Cout;
    if (splits > 1)
        reduce_split_kernel<<<(int)CDIV(n, 256), 256>>>(H, HP, n, splits);
    int nblk = CDIV(R, 256);
    bn_reduce_kernel<<<nblk, 256>>>(H, R, Cout, PB);
    bn_finalize_kernel<<<Cout, 256>>>(PB, nblk, Cout, R, g, bta, SS);
    if (doApply)
        bn_apply_kernel<<<(int)CDIV(n, 256), 256>>>(H, n, Cout - 1, SS);
}

template <int TCA, int TCB, int TCOUT>
static void run_tconv(const float* A, const int* mapA, const float* B,
                      const int* nb, int R, const float* W,
                      const float* g, const float* bta,
                      float* H, float* HP, float* PB, float* SS, int splits,
                      bool doApply) {
    dim3 grid(CDIV(R, 128), TCOUT / 64, splits);
    float* target = (splits == 1) ? H : HP;
    conv_tensor_kernel<TCA, TCB, TCOUT><<<grid, 256>>>(A, mapA, B, nb, R, W, target, splits);
    long long n = (long long)R * TCOUT;
    if (splits > 1)
        reduce_split_kernel<<<(int)CDIV(n, 256), 256>>>(H, HP, n, splits);
    int nblk = CDIV(R, 256);
    bn_reduce_kernel<<<nblk, 256>>>(H, R, TCOUT, PB);
    bn_finalize_kernel<<<TCOUT, 256>>>(PB, nblk, TCOUT, R, g, bta, SS);
    if (doApply)
        bn_apply_kernel<<<(int)CDIV(n, 256), 256>>>(H, n, TCOUT - 1, SS);
}

extern "C" void kernel_launch(void* const* d_in, const int* in_sizes, int n_in,
                              void* d_out, int out_size) {
    const float* x    = (const float*)d_in[0];
    const int*   nb32 = (const int*)d_in[1];
    const float* W_e1 = (const float*)d_in[2];
    const float* g_e1 = (const float*)d_in[3];
    const float* b_e1 = (const float*)d_in[4];
    const float* W_e2 = (const float*)d_in[5];
    const float* g_e2 = (const float*)d_in[6];
    const float* b_e2 = (const float*)d_in[7];
    const float* W_e3 = (const float*)d_in[8];
    const float* g_e3 = (const float*)d_in[9];
    const float* b_e3 = (const float*)d_in[10];
    const float* W_e4 = (const float*)d_in[11];
    const float* g_e4 = (const float*)d_in[12];
    const float* b_e4 = (const float*)d_in[13];
    const float* W_d3 = (const float*)d_in[14];
    const float* g_d3 = (const float*)d_in[15];
    const float* b_d3 = (const float*)d_in[16];
    const float* W_d2 = (const float*)d_in[17];
    const float* g_d2 = (const float*)d_in[18];
    const float* b_d2 = (const float*)d_in[19];
    const float* W_d1 = (const float*)d_in[20];
    const float* g_d1 = (const float*)d_in[21];
    const float* b_d1 = (const float*)d_in[22];
    const float* W_h  = (const float*)d_in[23];
    const float* b_h  = (const float*)d_in[24];
    float* out = (float*)d_out;

    float* gf = nullptr; cudaGetSymbolAddress((void**)&gf, g_f);
    int*   gi = nullptr; cudaGetSymbolAddress((void**)&gi, g_i);

    float* E1   = gf + F_E1;
    float* D1   = gf + F_D1;
    float* SC   = gf + F_SC;
    float* E1P  = gf + F_E1P;
    float* E2   = gf + F_E2;
    float* E2P  = gf + F_E2P;
    float* E3   = gf + F_E3;
    float* E3P  = gf + F_E3P;
    float* E4   = gf + F_E4;
    float* D3   = gf + F_D3;
    float* D2   = gf + F_D2;
    float* HP   = gf + F_HP;
    float* PB   = gf + F_PB;
    float* SS   = gf + F_SS;

    int* NB0  = gi + I_NB0;
    int* NB1  = gi + I_NB1;
    int* NB2  = gi + I_NB2;
    int* NB3  = gi + I_NB3;
    int* K1   = gi + I_K1;
    int* K2   = gi + I_K2;
    int* K3   = gi + I_K3;
    int* RM1  = gi + I_RM1;
    int* NN1  = gi + I_NN1;
    int* NN2  = gi + I_NN2;
    int* NN3  = gi + I_NN3;
    int* FEQ  = gi + I_FEQ;
    int* EQR  = gi + I_EQR;
    int* FKP  = gi + I_FKP;
    int* POS  = gi + I_POS;
    int* BSUM = gi + I_BSUM;
    unsigned* H1 = (unsigned*)(gi + I_H1);
    unsigned* H2 = (unsigned*)(gi + I_H2);
    int* SEL  = gi + I_SEL;

    const int nscanblk = CDIV(EN, 1024);  // 196

    // 0. reset accumulated state
    zero_hists_kernel<<<CDIV(16384 + 262144, 256), 256>>>(H1, H2);
    // 1. nb -> clipped int32 (input IS int32: jax x64 disabled)
    nbconv_kernel<<<CDIV(EN * 4, 256), 256>>>(nb32, EN * 4, EN, NB0);
    // 2. e1 = conv(x, nb0); BN apply fused with pool score
    run_conv(x, 5, NB0, EN, 64, W_e1, g_e1, b_e1, E1, HP, PB, SS, 1, false);
    bn_apply_score_kernel<<<CDIV(EN, 256), 256>>>(E1, EN, SS, SC);
    // 3. pool1: exact top-1500 by row norm
    hist1_kernel<<<782, 256>>>(SC, EN, H1);
    pick1_kernel<<<1, 1024>>>(H1, T1, SEL);
    hist2_kernel<<<782, 256>>>(SC, EN, H2, SEL);
    pick2_kernel<<<1, 1024>>>(H2, T1, SEL);
    flags_eq_kernel<<<CDIV(EN, 256), 256>>>(SC, EN, SEL, FEQ);
    scan_blk_kernel<<<nscanblk, 256>>>(FEQ, EQR, BSUM, EN);
    scan_top_kernel<<<1, 1024>>>(BSUM, nscanblk);
    scan_add_kernel<<<CDIV(EN, 256), 256>>>(EQR, BSUM, EN);
    flags_keep_kernel<<<CDIV(EN, 256), 256>>>(SC, EN, SEL, EQR, FKP);
    scan_blk_kernel<<<nscanblk, 256>>>(FKP, POS, BSUM, EN);
    scan_top_kernel<<<1, 1024>>>(BSUM, nscanblk);
    scan_add_kernel<<<CDIV(EN, 256), 256>>>(POS, BSUM, EN);
    scatter_kernel<<<CDIV(EN, 256), 256>>>(FKP, POS, EN, K1, RM1);
    gather_pool1_kernel<<<CDIV(T1 * 64, 256), 256>>>(E1, NB0, K1, RM1, T1, 64, E1P, NB1);
    // 4. e2 / pool2
    run_conv(E1P, 64, NB1, T1, 128, W_e2, g_e2, b_e2, E2, HP, PB, SS, 6, true);
    pool_small_kernel<<<1, 1024>>>(E2, NB1, T1, 128, T2, E2P, NB2, K2);
    // 5. e3 / pool3
    run_conv(E2P, 128, NB2, T2, 256, W_e3, g_e3, b_e3, E3, HP, PB, SS, 6, true);
    pool_small_kernel<<<1, 1024>>>(E3, NB2, T2, 256, T3, E3P, NB3, K3);
    // 6. e4
    run_conv(E3P, 256, NB3, T3, 512, W_e4, g_e4, b_e4, E4, HP, PB, SS, 8, true);
    // 7. d3 = tensor conv(virtual concat(unpool(e4), e3), nb2)
    nn_kernel<<<CDIV(T2, 256), 256>>>(K3, T3, T2, NN3);
    run_tconv<512, 256, 256>(E4, NN3, E3, NB2, T2, W_d3, g_d3, b_d3,
                             D3, HP, PB, SS, 12, true);
    // 8. d2 = tensor conv(virtual concat(unpool(d3), e2), nb1)
    nn_kernel<<<CDIV(T1, 256), 256>>>(K2, T2, T1, NN2);
    run_tconv<256, 128, 128>(D3, NN2, E2, NB1, T1, W_d2, g_d2, b_d2,
                             D2, HP, PB, SS, 8, true);
    // 9. d1 = tensor conv(virtual concat(unpool(d2), e1), nb0); BN fused w/ head
    nn_kernel<<<CDIV(EN, 256), 256>>>(K1, T1, EN, NN1);
    run_tconv<128, 64, 64>(D2, NN1, E1, NB0, EN, W_d1, g_d1, b_d1,
                           D1, HP, PB, SS, 1, false);
    // 10. head (reads pre-BN d1, applies BN+ReLU inline)
    bn_apply_head_kernel<<<CDIV(EN, 256), 256>>>(D1, EN, SS, W_h, b_h, out);
}

// round 17
// speedup vs baseline: 1.0494x; 1.0494x over previous
#include <cuda_runtime.h>
#include <cuda_bf16.h>

// ---------------------------------------------------------------------------
// GeoConvNet3DMeshSeg — full mesh U-Net forward.
// R17: R15 baseline (best: 1693us) + ONE change: d1 tensor kernel stages
//      weights pre-converted to tf32 hi/lo in fragment order (inner loop =
//      2x LDS.64 + 3 MMA per n-tile, zero weight cvts). d2/d3 reverted to the
//      proven scalar CONCAT path. Encoder layers scalar (feed pool ties).
// NOTE: nb input is INT32 (jax downcasts int64 -> int32 with x64 disabled).
// ---------------------------------------------------------------------------

#define CDIV(a, b) (((a) + (b) - 1) / (b))

static const int EN = 200000;
static const int T1 = 1500, T2 = 750, T3 = 375;

// ---------------- float arena ----------------
static const long long F_E1   = 0;                              // EN*64
static const long long F_D1   = F_E1   + (long long)EN * 64;    // EN*64
static const long long F_SC   = F_D1   + (long long)EN * 64;    // EN
static const long long F_E1P  = F_SC   + EN;                    // T1*64
static const long long F_E2   = F_E1P  + (long long)T1 * 64;    // T1*128
static const long long F_E2P  = F_E2   + (long long)T1 * 128;   // T2*128
static const long long F_E3   = F_E2P  + (long long)T2 * 128;   // T2*256
static const long long F_E3P  = F_E3   + (long long)T2 * 256;   // T3*256
static const long long F_E4   = F_E3P  + (long long)T3 * 256;   // T3*512
static const long long F_D3   = F_E4   + (long long)T3 * 512;   // T2*256
static const long long F_D2   = F_D3   + (long long)T2 * 256;   // T1*128
static const long long F_HP   = F_D2   + (long long)T1 * 128;   // split-K partials
static const long long F_PB   = F_HP   + 2600000;               // BN partials
static const long long F_SS   = F_PB   + 140000;                // BN scale/shift
static const long long F_TOT  = F_SS   + 2048;

// ---------------- int arena ----------------
static const long long I_NB0  = 0;                              // EN*4
static const long long I_NB1  = I_NB0 + (long long)EN * 4;      // T1*4
static const long long I_NB2  = I_NB1 + T1 * 4;                 // T2*4
static const long long I_NB3  = I_NB2 + T2 * 4;                 // T3*4
static const long long I_K1   = I_NB3 + T3 * 4;                 // T1
static const long long I_K2   = I_K1 + T1;                      // T2
static const long long I_K3   = I_K2 + T2;                      // T3
static const long long I_RM1  = I_K3 + T3;                      // EN
static const long long I_NN1  = I_RM1 + EN;                     // EN
static const long long I_NN2  = I_NN1 + EN;                     // T1
static const long long I_NN3  = I_NN2 + T1;                     // T2
static const long long I_FEQ  = I_NN3 + T2;                     // EN
static const long long I_EQR  = I_FEQ + EN;                     // EN
static const long long I_FKP  = I_EQR + EN;                     // EN
static const long long I_POS  = I_FKP + EN;                     // EN
static const long long I_BSUM = I_POS + EN;                     // 1024
static const long long I_H1   = I_BSUM + 1024;                  // 16384
static const long long I_H2   = I_H1 + 16384;                   // 262144
static const long long I_SEL  = I_H2 + 262144;                  // 8
static const long long I_TOT  = I_SEL + 8;

__device__ __align__(16) float g_f[F_TOT];
__device__ __align__(16) int   g_i[I_TOT];

// ---------------------------------------------------------------------------
// misc small kernels
// ---------------------------------------------------------------------------
__global__ void zero_hists_kernel(unsigned* h1, unsigned* h2) {
    int n = 16384 + 262144;
    for (int i = blockIdx.x * blockDim.x + threadIdx.x; i < n; i += gridDim.x * blockDim.x) {
        if (i < 16384) h1[i] = 0u; else h2[i - 16384] = 0u;
    }
}

__global__ void nbconv_kernel(const int* __restrict__ nb32, int n4, int E,
                              int* __restrict__ out) {
    int i = blockIdx.x * blockDim.x + threadIdx.x;
    if (i >= n4) return;
    int v = nb32[i];
    if (v < 0) v = 0;
    if (v >= E) v = E - 1;
    out[i] = v;
}

// ---------------------------------------------------------------------------
// Scalar double-buffered conv (R13/R15, proven) — all layers except d1.
// feature(row,c) = CONCAT ? (c<CA ? A[mapA[row]*CA+c] : B[row*CB+(c-CA)])
//                         : A[row*CA+c]
// ---------------------------------------------------------------------------
#define MM4(A0, A1, A2, A3, rv, cv)                                          \
    A0.x = fmaf(rv.x, cv.x, A0.x); A0.y = fmaf(rv.x, cv.y, A0.y);            \
    A0.z = fmaf(rv.x, cv.z, A0.z); A0.w = fmaf(rv.x, cv.w, A0.w);            \
    A1.x = fmaf(rv.y, cv.x, A1.x); A1.y = fmaf(rv.y, cv.y, A1.y);            \
    A1.z = fmaf(rv.y, cv.z, A1.z); A1.w = fmaf(rv.y, cv.w, A1.w);            \
    A2.x = fmaf(rv.z, cv.x, A2.x); A2.y = fmaf(rv.z, cv.y, A2.y);            \
    A2.z = fmaf(rv.z, cv.z, A2.z); A2.w = fmaf(rv.z, cv.w, A2.w);            \
    A3.x = fmaf(rv.w, cv.x, A3.x); A3.y = fmaf(rv.w, cv.y, A3.y);            \
    A3.z = fmaf(rv.w, cv.z, A3.z); A3.w = fmaf(rv.w, cv.w, A3.w);

template <int KCH, bool CONCAT>
__global__ __launch_bounds__(256) void conv_kernel(
    const float* __restrict__ A, int CA, const int* __restrict__ mapA,
    const float* __restrict__ B, int CB,
    const int* __restrict__ nb, int R, int Cout, const float* __restrict__ W,
    float* __restrict__ Hout, int splits)
{
    const int C = CONCAT ? (CA + CB) : CA;
    const int IT = KCH / 4;
    const int LSH = (KCH == 32) ? 5 : ((KCH == 16) ? 4 : 3);
    const int SFSZ = 2 * KCH * 68;
    const int SWSZ = 2 * KCH * 64;
    __shared__ int   SN[256];
    __shared__ int   SNA[CONCAT ? 256 : 1];
    __shared__ int   SMA[CONCAT ? 64 : 1];
    __shared__ float SF[2 * 2 * KCH * 68];
    __shared__ float SW[2 * 2 * KCH * 64];

    const int tid  = threadIdx.x;
    const int row0 = blockIdx.x * 64;
    const int col0 = blockIdx.y * 64;
    const int zid  = blockIdx.z;
    const int tr = tid >> 4, tc = tid & 15;
    const int nchunk = (C + KCH - 1) / KCH;
    const int totalu = 3 * nchunk;

    float4 a00 = {0,0,0,0}, a01 = a00, a02 = a00, a03 = a00;
    float fa[IT], fb[IT], wa[IT], wb[IT];

    {
        int gi = row0 + (tid >> 2);
        int nbv = (gi < R) ? nb[gi * 4 + (tid & 3)] : 0;
        SN[tid] = nbv;
        if (CONCAT) {
            SNA[tid] = mapA[nbv];
            if (tid < 64) {
                int g2 = row0 + tid;
                SMA[tid] = mapA[(g2 < R) ? g2 : 0];
            }
        }
    }
    __syncthreads();

    auto prefetch = [&](int u) {
        int st = u / nchunk, ck = u - st * nchunk;
        int k0 = ck * KCH;
        #pragma unroll
        for (int it = 0; it < IT; it++) {
            int e = tid + it * 256;
            int kk = e & (KCH - 1), row = e >> LSH;
            int ch = k0 + kk;
            int gi = row0 + row;
            bool ok = (gi < R) && (ch < C);
            if (st == 0) {
                float v = 0.f;
                if (ok) {
                    if (!CONCAT || ch < CA) {
                        int ra = CONCAT ? SMA[row] : gi;
                        v = A[(size_t)ra * CA + ch];
                    } else {
                        v = B[(size_t)gi * CB + (ch - CA)];
                    }
                }
                fa[it] = v; fb[it] = v;
            } else {
                float a = 0.f, b = 0.f;
                if (ok) {
                    int j0 = row * 4 + (st - 1) * 2;
                    if (!CONCAT || ch < CA) {
                        int r0a = CONCAT ? SNA[j0]     : SN[j0];
                        int r1a = CONCAT ? SNA[j0 + 1] : SN[j0 + 1];
                        a = A[(size_t)r0a * CA + ch];
                        b = A[(size_t)r1a * CA + ch];
                    } else {
                        a = B[(size_t)SN[j0]     * CB + (ch - CA)];
                        b = B[(size_t)SN[j0 + 1] * CB + (ch - CA)];
                    }
                }
                fa[it] = a; fb[it] = b;
            }
        }
        int part0 = (st == 0) ? 0 : (2 * st - 1);
        #pragma unroll
        for (int it = 0; it < IT; it++) {
            int e = tid + it * 256;
            int cc = e & 63, kk = e >> 6;
            int ch = k0 + kk;
            bool okc = (ch < C);
            wa[it] = okc ? W[(size_t)(part0 * C + ch) * Cout + col0 + cc] : 0.f;
            wb[it] = (st && okc) ? W[(size_t)((part0 + 1) * C + ch) * Cout + col0 + cc] : 0.f;
        }
    };

    auto stage = [&](int u, int p) {
        int st = u / nchunk;
        float* SFb = SF + p * SFSZ;
        float* SWb = SW + p * SWSZ;
        #pragma unroll
        for (int it = 0; it < IT; it++) {
            int e = tid + it * 256;
            int kk = e & (KCH - 1), row = e >> LSH;
            if (st == 0) {
                SFb[kk * 68 + row] = fa[it];
            } else {
                SFb[kk * 68 + row]            = fminf(fa[it], fb[it]);
                SFb[KCH * 68 + kk * 68 + row] = fmaxf(fa[it], fb[it]);
            }
        }
        #pragma unroll
        for (int it = 0; it < IT; it++) {
            int e = tid + it * 256;
            int cc = e & 63, kk = e >> 6;
            SWb[kk * 64 + cc] = wa[it];
            if (st) SWb[KCH * 64 + kk * 64 + cc] = wb[it];
        }
    };

    int u = zid;
    int p = 0;
    if (u < totalu) prefetch(u);
    while (u < totalu) {
        int unext = u + splits;
        stage(u, p);
        if (unext < totalu) prefetch(unext);
        __syncthreads();
        int st = u / nchunk;
        const float* SFb = SF + p * SFSZ;
        const float* SWb = SW + p * SWSZ;
        if (st == 0) {
            #pragma unroll
            for (int kk = 0; kk < KCH; kk++) {
                float4 rv = *(const float4*)&SFb[kk * 68 + tr * 4];
                float4 cv = *(const float4*)&SWb[kk * 64 + tc * 4];
                MM4(a00, a01, a02, a03, rv, cv)
            }
        } else {
            #pragma unroll
            for (int kk = 0; kk < KCH; kk++) {
                float4 rv = *(const float4*)&SFb[kk * 68 + tr * 4];
                float4 cv = *(const float4*)&SWb[kk * 64 + tc * 4];
                MM4(a00, a01, a02, a03, rv, cv)
                float4 rv2 = *(const float4*)&SFb[KCH * 68 + kk * 68 + tr * 4];
                float4 cv2 = *(const float4*)&SWb[KCH * 64 + kk * 64 + tc * 4];
                MM4(a00, a01, a02, a03, rv2, cv2)
            }
        }
        u = unext;
        p ^= 1;
    }

    float* O = Hout + (size_t)zid * R * Cout;
    float4 rows[4] = {a00, a01, a02, a03};
    #pragma unroll
    for (int qr = 0; qr < 4; qr++) {
        int gi = row0 + tr * 4 + qr;
        if (gi < R)
            *(float4*)&O[(size_t)gi * Cout + col0 + tc * 4] = rows[qr];
    }
}

// ---------------------------------------------------------------------------
// d1 tensor conv: split-TF32 mma.sync.m16n8k8 (3 passes: hh + hl + lh).
// Block 128 rows x 64 cols, 8 warps; warp = 16 rows x 64 cols (8 n-tiles).
// Weights pre-converted to tf32 hi/lo at STAGE time in fragment order ->
// inner loop per n-tile = 2x LDS.64 + 3 MMA (zero weight conversions).
// ---------------------------------------------------------------------------
__device__ __forceinline__ unsigned tf32cvt(float x) {
    unsigned r; asm("cvt.rna.tf32.f32 %0, %1;" : "=r"(r) : "f"(x)); return r;
}
#define MMA_TF32(c0, c1, c2, c3, a0, a1, a2, a3, b0, b1)                      \
    asm("mma.sync.aligned.m16n8k8.row.col.f32.tf32.tf32.f32 "                 \
        "{%0,%1,%2,%3}, {%4,%5,%6,%7}, {%8,%9}, {%0,%1,%2,%3};"               \
        : "+f"(c0), "+f"(c1), "+f"(c2), "+f"(c3)                              \
        : "r"(a0), "r"(a1), "r"(a2), "r"(a3), "r"(b0), "r"(b1))

__global__ __launch_bounds__(256) void conv_d1_tensor_kernel(
    const float* __restrict__ A, const int* __restrict__ mapA,
    const float* __restrict__ B,
    const int* __restrict__ nb, int R, const float* __restrict__ W,
    float* __restrict__ Hout)
{
    const int CA = 128, CB = 64, C = 192, Cout = 64;
    const int KCH = 8, nchunk = C / KCH, totalu = 3 * nchunk;  // 24, 72
    const int SFSZ = 2 * KCH * 132;   // one buffer: 2 planes x 8 kk x 132
    __shared__ int      SN[512];
    __shared__ int      SNA[512];
    __shared__ int      SMA[128];
    __shared__ float    SF[2 * 2 * KCH * 132];
    __shared__ unsigned SWhi[2 * 2 * 512];  // [buf][plane][fragment slot]
    __shared__ unsigned SWlo[2 * 2 * 512];

    const int tid  = threadIdx.x;
    const int row0 = blockIdx.x * 128;
    const int wid = tid >> 5, lane = tid & 31;

    float acc[8][4];
    #pragma unroll
    for (int n = 0; n < 8; n++) { acc[n][0] = acc[n][1] = acc[n][2] = acc[n][3] = 0.f; }

    float fa[4], fb[4], wa[2], wb[2];

    #pragma unroll
    for (int it = 0; it < 2; it++) {
        int e = tid + it * 256;                 // 128 rows x 4 nbrs
        int gi = row0 + (e >> 2);
        int nbv = (gi < R) ? nb[gi * 4 + (e & 3)] : 0;
        SN[e] = nbv;
        SNA[e] = mapA[nbv];
    }
    if (tid < 128) {
        int g2 = row0 + tid;
        SMA[tid] = mapA[(g2 < R) ? g2 : 0];
    }
    __syncthreads();

    auto prefetch = [&](int u) {
        int st = u / nchunk, ck = u - st * nchunk;
        int k0 = ck * KCH;
        #pragma unroll
        for (int it = 0; it < 4; it++) {
            int e = tid + it * 256;             // 128 rows x 8 kk
            int kk = e & 7, row = e >> 3;
            int ch = k0 + kk;
            int gi = row0 + row;
            bool ok = (gi < R);
            if (st == 0) {
                float v = 0.f;
                if (ok) v = (ch < CA) ? A[(size_t)SMA[row] * CA + ch]
                                      : B[(size_t)gi * CB + (ch - CA)];
                fa[it] = v; fb[it] = v;
            } else {
                float a = 0.f, b = 0.f;
                if (ok) {
                    int j0 = row * 4 + (st - 1) * 2;
                    if (ch < CA) {
                        a = A[(size_t)SNA[j0]     * CA + ch];
                        b = A[(size_t)SNA[j0 + 1] * CA + ch];
                    } else {
                        a = B[(size_t)SN[j0]     * CB + (ch - CA)];
                        b = B[(size_t)SN[j0 + 1] * CB + (ch - CA)];
                    }
                }
                fa[it] = a; fb[it] = b;
            }
        }
        int part0 = (st == 0) ? 0 : (2 * st - 1);
        #pragma unroll
        for (int it = 0; it < 2; it++) {
            int e = tid + it * 256;             // 8 kk x 64 cc
            int cc = e & 63, kk = e >> 6;
            int ch = k0 + kk;
            wa[it] = W[(size_t)(part0 * C + ch) * Cout + cc];
            wb[it] = st ? W[(size_t)((part0 + 1) * C + ch) * Cout + cc] : 0.f;
        }
    };

    auto stage = [&](int u, int p) {
        int st = u / nchunk;
        float* SFb = SF + p * SFSZ;
        unsigned* SHb = SWhi + p * 1024;
        unsigned* SLb = SWlo + p * 1024;
        #pragma unroll
        for (int it = 0; it < 4; it++) {
            int e = tid + it * 256;
            int kk = e & 7, row = e >> 3;
            if (st == 0) {
                SFb[kk * 132 + row] = fa[it];
            } else {
                SFb[kk * 132 + row]             = fminf(fa[it], fb[it]);
                SFb[KCH * 132 + kk * 132 + row] = fmaxf(fa[it], fb[it]);
            }
        }
        #pragma unroll
        for (int it = 0; it < 2; it++) {
            int e = tid + it * 256;
            int cc = e & 63, kk = e >> 6;
            int n = cc >> 3, r = cc & 7;
            int slot = n * 64 + (r * 4 + (kk & 3)) * 2 + (kk >> 2);
            unsigned hi0 = tf32cvt(wa[it]);
            SHb[slot] = hi0;
            SLb[slot] = tf32cvt(wa[it] - __uint_as_float(hi0));
            if (st) {
                unsigned hi1 = tf32cvt(wb[it]);
                SHb[512 + slot] = hi1;
                SLb[512 + slot] = tf32cvt(wb[it] - __uint_as_float(hi1));
            }
        }
    };

    int u = 0, p = 0;
    prefetch(0);
    while (u < totalu) {
        int unext = u + 1;
        stage(u, p);
        if (unext < totalu) prefetch(unext);
        __syncthreads();
        int st = u / nchunk;
        int planes = st ? 2 : 1;
        const float* SFb = SF + p * SFSZ;
        const unsigned* SHb = SWhi + p * 1024;
        const unsigned* SLb = SWlo + p * 1024;
        #pragma unroll
        for (int plane = 0; plane < 2; plane++) {
            if (plane >= planes) break;
            const float* F = SFb + plane * KCH * 132;
            const unsigned* Whi = SHb + plane * 512;
            const unsigned* Wlo = SLb + plane * 512;
            int r0 = (wid << 4) + (lane >> 2);
            int kq = lane & 3;
            float a0f = F[kq * 132 + r0];
            float a1f = F[kq * 132 + r0 + 8];
            float a2f = F[(kq + 4) * 132 + r0];
            float a3f = F[(kq + 4) * 132 + r0 + 8];
            unsigned ah0 = tf32cvt(a0f), ah1 = tf32cvt(a1f);
            unsigned ah2 = tf32cvt(a2f), ah3 = tf32cvt(a3f);
            unsigned al0 = tf32cvt(a0f - __uint_as_float(ah0));
            unsigned al1 = tf32cvt(a1f - __uint_as_float(ah1));
            unsigned al2 = tf32cvt(a2f - __uint_as_float(ah2));
            unsigned al3 = tf32cvt(a3f - __uint_as_float(ah3));
            #pragma unroll
            for (int n = 0; n < 8; n++) {
                uint2 bh = *(const uint2*)&Whi[n * 64 + lane * 2];
                uint2 bl = *(const uint2*)&Wlo[n * 64 + lane * 2];
                MMA_TF32(acc[n][0], acc[n][1], acc[n][2], acc[n][3],
                         ah0, ah1, ah2, ah3, bh.x, bh.y);
                MMA_TF32(acc[n][0], acc[n][1], acc[n][2], acc[n][3],
                         ah0, ah1, ah2, ah3, bl.x, bl.y);
                MMA_TF32(acc[n][0], acc[n][1], acc[n][2], acc[n][3],
                         al0, al1, al2, al3, bh.x, bh.y);
            }
        }
        u = unext;
        p ^= 1;
    }

    // epilogue: fragment layout -> Hout
    int rbase = row0 + (wid << 4) + (lane >> 2);
    #pragma unroll
    for (int n = 0; n < 8; n++) {
        int col = n * 8 + (lane & 3) * 2;
        if (rbase < R) {
            float2 v = {acc[n][0], acc[n][1]};
            *(float2*)&Hout[(size_t)rbase * 64 + col] = v;
        }
        if (rbase + 8 < R) {
            float2 v = {acc[n][2], acc[n][3]};
            *(float2*)&Hout[(size_t)(rbase + 8) * 64 + col] = v;
        }
    }
}

__global__ void reduce_split_kernel(float* __restrict__ H, const float* __restrict__ part,
                                    long long n, int splits) {
    long long i = (long long)blockIdx.x * blockDim.x + threadIdx.x;
    long long stride = (long long)gridDim.x * blockDim.x;
    for (; i < n; i += stride) {
        float s = 0.f;
        for (int z = 0; z < splits; z++) s += part[(long long)z * n + i];
        H[i] = s;
    }
}

// ---------------------------------------------------------------------------
// BatchNorm (training stats) + ReLU : deterministic two-level reduction
// ---------------------------------------------------------------------------
__global__ void bn_reduce_kernel(const float* __restrict__ H, int R, int Cout,
                                 float* __restrict__ partial) {
    int b = blockIdx.x;
    int r0 = b * 256;
    int rend = min(R, r0 + 256);
    for (int c = threadIdx.x; c < Cout; c += 256) {
        float s = 0.f, s2 = 0.f;
        for (int r = r0; r < rend; r++) {
            float v = H[(size_t)r * Cout + c];
            s += v; s2 += v * v;
        }
        partial[((size_t)b * Cout + c) * 2]     = s;
        partial[((size_t)b * Cout + c) * 2 + 1] = s2;
    }
}

__global__ void bn_finalize_kernel(const float* __restrict__ partial, int nblk, int Cout,
                                   int R, const float* __restrict__ g,
                                   const float* __restrict__ bta, float* __restrict__ ss) {
    __shared__ float s1[256], s2s[256];
    int c = blockIdx.x;
    float s = 0.f, s2 = 0.f;
    for (int b = threadIdx.x; b < nblk; b += 256) {
        s  += partial[((size_t)b * Cout + c) * 2];
        s2 += partial[((size_t)b * Cout + c) * 2 + 1];
    }
    s1[threadIdx.x] = s; s2s[threadIdx.x] = s2;
    __syncthreads();
    for (int off = 128; off > 0; off >>= 1) {
        if (threadIdx.x < off) {
            s1[threadIdx.x] += s1[threadIdx.x + off];
            s2s[threadIdx.x] += s2s[threadIdx.x + off];
        }
        __syncthreads();
    }
    if (threadIdx.x == 0) {
        float mu  = s1[0] / (float)R;
        float var = s2s[0] / (float)R - mu * mu;
        if (var < 0.f) var = 0.f;
        float sc = rsqrtf(var + 1e-5f) * g[c];
        ss[c * 2]     = sc;
        ss[c * 2 + 1] = bta[c] - mu * sc;
    }
}

__global__ void bn_apply_kernel(float* __restrict__ H, long long n, int Cmask,
                                const float* __restrict__ ss) {
    long long i = (long long)blockIdx.x * blockDim.x + threadIdx.x;
    long long stride = (long long)gridDim.x * blockDim.x;
    for (; i < n; i += stride) {
        int c = (int)(i & Cmask);
        float h = H[i] * ss[c * 2] + ss[c * 2 + 1];
        H[i] = fmaxf(h, 0.f);
    }
}

// Fused: BN+ReLU in place on e1 (Cout=64) AND row L2-norm score.
__global__ __launch_bounds__(256) void bn_apply_score_kernel(float* __restrict__ H, int R,
                                                             const float* __restrict__ ss,
                                                             float* __restrict__ sc) {
    __shared__ float s2[128];
    if (threadIdx.x < 128) s2[threadIdx.x] = ss[threadIdx.x];
    __syncthreads();
    int r = blockIdx.x * 256 + threadIdx.x;
    if (r >= R) return;
    float4* row = (float4*)(H + (size_t)r * 64);
    float acc = 0.f;
    #pragma unroll
    for (int q = 0; q < 16; q++) {
        float4 v = row[q];
        int c = q * 4;
        v.x = fmaxf(v.x * s2[(c + 0) * 2] + s2[(c + 0) * 2 + 1], 0.f);
        v.y = fmaxf(v.y * s2[(c + 1) * 2] + s2[(c + 1) * 2 + 1], 0.f);
        v.z = fmaxf(v.z * s2[(c + 2) * 2] + s2[(c + 2) * 2 + 1], 0.f);
        v.w = fmaxf(v.w * s2[(c + 3) * 2] + s2[(c + 3) * 2 + 1], 0.f);
        acc += v.x * v.x + v.y * v.y + v.z * v.z + v.w * v.w;
        row[q] = v;
    }
    sc[r] = sqrtf(acc);
}

// Fused: BN+ReLU on d1 (read-only) + head GEMV -> out[R,4].
__global__ __launch_bounds__(256) void bn_apply_head_kernel(const float* __restrict__ H, int R,
                                                            const float* __restrict__ ss,
                                                            const float* __restrict__ Wh,
                                                            const float* __restrict__ bh,
                                                            float* __restrict__ out) {
    __shared__ float s2[128];
    __shared__ float sw[256];
    __shared__ float sb[4];
    if (threadIdx.x < 128) s2[threadIdx.x] = ss[threadIdx.x];
    sw[threadIdx.x] = Wh[threadIdx.x];
    if (threadIdx.x < 4) sb[threadIdx.x] = bh[threadIdx.x];
    __syncthreads();
    int r = blockIdx.x * 256 + threadIdx.x;
    if (r >= R) return;
    const float4* row = (const float4*)(H + (size_t)r * 64);
    float a0 = sb[0], a1 = sb[1], a2 = sb[2], a3 = sb[3];
    #pragma unroll
    for (int q = 0; q < 16; q++) {
        float4 v = row[q];
        int c = q * 4;
        v.x = fmaxf(v.x * s2[(c + 0) * 2] + s2[(c + 0) * 2 + 1], 0.f);
        v.y = fmaxf(v.y * s2[(c + 1) * 2] + s2[(c + 1) * 2 + 1], 0.f);
        v.z = fmaxf(v.z * s2[(c + 2) * 2] + s2[(c + 2) * 2 + 1], 0.f);
        v.w = fmaxf(v.w * s2[(c + 3) * 2] + s2[(c + 3) * 2 + 1], 0.f);
        a0 += v.x * sw[(c + 0) * 4 + 0] + v.y * sw[(c + 1) * 4 + 0] + v.z * sw[(c + 2) * 4 + 0] + v.w * sw[(c + 3) * 4 + 0];
        a1 += v.x * sw[(c + 0) * 4 + 1] + v.y * sw[(c + 1) * 4 + 1] + v.z * sw[(c + 2) * 4 + 1] + v.w * sw[(c + 3) * 4 + 1];
        a2 += v.x * sw[(c + 0) * 4 + 2] + v.y * sw[(c + 1) * 4 + 2] + v.z * sw[(c + 2) * 4 + 2] + v.w * sw[(c + 3) * 4 + 2];
        a3 += v.x * sw[(c + 0) * 4 + 3] + v.y * sw[(c + 1) * 4 + 3] + v.z * sw[(c + 2) * 4 + 3] + v.w * sw[(c + 3) * 4 + 3];
    }
    float4 o = {a0, a1, a2, a3};
    *(float4*)&out[(size_t)r * 4] = o;
}

// ---------------------------------------------------------------------------
// Pool 1 (200000 -> 1500): exact radix select on float bits + scan compaction
// ---------------------------------------------------------------------------
__global__ void hist1_kernel(const float* __restrict__ sc, int n, unsigned* __restrict__ h1) {
    int i = blockIdx.x * blockDim.x + threadIdx.x;
    int stride = gridDim.x * blockDim.x;
    for (; i < n; i += stride) {
        unsigned u = __float_as_uint(sc[i]);
        atomicAdd(&h1[u >> 18], 1u);
    }
}

__global__ __launch_bounds__(1024) void pick1_kernel(const unsigned* __restrict__ h1,
                                                     int k, int* __restrict__ sel) {
    __shared__ unsigned cs[1024];
    int t = threadIdx.x;
    unsigned s = 0;
    for (int j = 0; j < 16; j++) s += h1[t * 16 + j];
    cs[t] = s;
    __syncthreads();
    if (t == 0) {
        unsigned cum = 0;
        int chunk = 0;
        for (int q = 1023; q >= 0; q--) {
            if (cum + cs[q] >= (unsigned)k) { chunk = q; break; }
            cum += cs[q];
        }
        int bin = chunk * 16;
        for (int j = 15; j >= 0; j--) {
            unsigned hv = h1[chunk * 16 + j];
            if (cum + hv >= (unsigned)k) { bin = chunk * 16 + j; break; }
            cum += hv;
        }
        sel[0] = bin;
        sel[1] = (int)cum;
    }
}

__global__ void hist2_kernel(const float* __restrict__ sc, int n,
                             unsigned* __restrict__ h2, const int* __restrict__ sel) {
    unsigned bin = (unsigned)sel[0];
    int i = blockIdx.x * blockDim.x + threadIdx.x;
    int stride = gridDim.x * blockDim.x;
    for (; i < n; i += stride) {
        unsigned u = __float_as_uint(sc[i]);
        if ((u >> 18) == bin) atomicAdd(&h2[u & 0x3FFFFu], 1u);
    }
}

__global__ __launch_bounds__(1024) void pick2_kernel(const unsigned* __restrict__ h2,
                                                     int k, int* __restrict__ sel) {
    __shared__ unsigned cs[1024];
    int t = threadIdx.x;
    unsigned s = 0;
    for (int j = 0; j < 256; j++) s += h2[t * 256 + j];
    cs[t] = s;
    __syncthreads();
    if (t == 0) {
        unsigned cum = (unsigned)sel[1];
        int chunk = 0;
        for (int q = 1023; q >= 0; q--) {
            if (cum + cs[q] >= (unsigned)k) { chunk = q; break; }
            cum += cs[q];
        }
        int L = chunk * 256;
        for (int j = 255; j >= 0; j--) {
            unsigned hv = h2[chunk * 256 + j];
            if (cum + hv >= (unsigned)k) { L = chunk * 256 + j; break; }
            cum += hv;
        }
        sel[2] = (int)(((unsigned)sel[0] << 18) | (unsigned)L);
        sel[3] = k - (int)cum;
    }
}

__global__ void flags_eq_kernel(const float* __restrict__ sc, int n,
                                const int* __restrict__ sel, int* __restrict__ f) {
    unsigned thr = (unsigned)sel[2];
    int i = blockIdx.x * blockDim.x + threadIdx.x;
    if (i < n) f[i] = (__float_as_uint(sc[i]) == thr) ? 1 : 0;
}

__global__ void flags_keep_kernel(const float* __restrict__ sc, int n,
                                  const int* __restrict__ sel,
                                  const int* __restrict__ eqrank, int* __restrict__ f) {
    unsigned thr = (unsigned)sel[2];
    int need = sel[3];
    int i = blockIdx.x * blockDim.x + threadIdx.x;
    if (i < n) {
        unsigned u = __float_as_uint(sc[i]);
        f[i] = (u > thr || (u == thr && eqrank[i] < need)) ? 1 : 0;
    }
}

__global__ __launch_bounds__(256) void scan_blk_kernel(const int* __restrict__ in,
                                                       int* __restrict__ out,
                                                       int* __restrict__ bsum, int n) {
    __shared__ int s[256];
    int blk = blockIdx.x;
    int base = blk * 1024;
    int v[4], tsum = 0;
    #pragma unroll
    for (int q = 0; q < 4; q++) {
        int idx = base + threadIdx.x * 4 + q;
        v[q] = (idx < n) ? in[idx] : 0;
        tsum += v[q];
    }
    s[threadIdx.x] = tsum;
    __syncthreads();
    for (int off = 1; off < 256; off <<= 1) {
        int t = (threadIdx.x >= off) ? s[threadIdx.x - off] : 0;
        __syncthreads();
        s[threadIdx.x] += t;
        __syncthreads();
    }
    int run = s[threadIdx.x] - tsum;
    if (threadIdx.x == 255) bsum[blk] = s[255];
    #pragma unroll
    for (int q = 0; q < 4; q++) {
        int idx = base + threadIdx.x * 4 + q;
        if (idx < n) out[idx] = run;
        run += v[q];
    }
}

__global__ void scan_top_kernel(int* __restrict__ bsum, int nb) {
    __shared__ int s[1024];
    for (int i = threadIdx.x; i < nb; i += blockDim.x) s[i] = bsum[i];
    __syncthreads();
    if (threadIdx.x == 0) {
        int run = 0;
        for (int i = 0; i < nb; i++) { int v = s[i]; s[i] = run; run += v; }
    }
    __syncthreads();
    for (int i = threadIdx.x; i < nb; i += blockDim.x) bsum[i] = s[i];
}

__global__ void scan_add_kernel(int* __restrict__ out, const int* __restrict__ bsum, int n) {
    int i = blockIdx.x * blockDim.x + threadIdx.x;
    if (i < n) out[i] += bsum[i >> 10];
}

__global__ void scatter_kernel(const int* __restrict__ fkp, const int* __restrict__ pos,
                               int n, int* __restrict__ keep, int* __restrict__ remap) {
    int i = blockIdx.x * blockDim.x + threadIdx.x;
    if (i >= n) return;
    if (fkp[i]) { int p = pos[i]; keep[p] = i; remap[i] = p; }
    else remap[i] = -1;
}

__global__ void gather_pool1_kernel(const float* __restrict__ X, const int* __restrict__ nb0,
                                    const int* __restrict__ keep, const int* __restrict__ remap,
                                    int k, int C, float* __restrict__ Xp, int* __restrict__ nbp) {
    int i = blockIdx.x * blockDim.x + threadIdx.x;
    int stride = gridDim.x * blockDim.x;
    for (int e = i; e < k * C; e += stride) {
        int j = e / C, c = e - j * C;
        Xp[e] = X[(size_t)keep[j] * C + c];
    }
    for (int e = i; e < k * 4; e += stride) {
        int j = e >> 2, t = e & 3;
        int v = remap[nb0[keep[j] * 4 + t]];
        nbp[e] = (v < 0) ? j : v;
    }
}

// ---------------------------------------------------------------------------
// Small pools (single block, O(n^2) exact rank)
// ---------------------------------------------------------------------------
__global__ __launch_bounds__(1024) void pool_small_kernel(
    const float* __restrict__ X, const int* __restrict__ nbin,
    int R, int C, int k,
    float* __restrict__ Xp, int* __restrict__ nbp, int* __restrict__ keep)
{
    __shared__ float sSc[1536];
    __shared__ int   sFlag[1536];
    __shared__ int   sPos[1536];
    int t = threadIdx.x;
    for (int i = t; i < R; i += 1024) {
        const float* row = X + (size_t)i * C;
        float s = 0.f;
        for (int c = 0; c < C; c++) { float v = row[c]; s += v * v; }
        sSc[i] = sqrtf(s);
    }
    __syncthreads();
    for (int i = t; i < R; i += 1024) {
        float mine = sSc[i];
        int cnt = 0;
        for (int j = 0; j < R; j++) {
            float sj = sSc[j];
            cnt += (sj > mine || (sj == mine && j < i)) ? 1 : 0;
        }
        sFlag[i] = (cnt < k) ? 1 : 0;
    }
    __syncthreads();
    for (int i = t; i < R; i += 1024) {
        int p = 0;
        for (int j = 0; j < i; j++) p += sFlag[j];
        sPos[i] = p;
    }
    __syncthreads();
    for (int i = t; i < R; i += 1024)
        if (sFlag[i]) keep[sPos[i]] = i;
    for (long long e = t; e < (long long)R * C; e += 1024) {
        int i = (int)(e / C), c = (int)(e - (long long)i * C);
        if (sFlag[i]) Xp[(size_t)sPos[i] * C + c] = X[e];
    }
    for (int e = t; e < R * 4; e += 1024) {
        int i = e >> 2, tt = e & 3;
        if (sFlag[i]) {
            int nbv = nbin[e];
            int v = sFlag[nbv] ? sPos[nbv] : -1;
            nbp[sPos[i] * 4 + tt] = (v < 0) ? sPos[i] : v;
        }
    }
}

// ---------------------------------------------------------------------------
// Unpool: nearest kept index (searchsorted-left + tie to lower)
// ---------------------------------------------------------------------------
__global__ void nn_kernel(const int* __restrict__ keep, int K, int Ef, int* __restrict__ nn) {
    int i = blockIdx.x * blockDim.x + threadIdx.x;
    if (i >= Ef) return;
    int lo = 0, hi = K;
    while (lo < hi) {
        int m = (lo + hi) >> 1;
        if (keep[m] < i) lo = m + 1; else hi = m;
    }
    int left = lo - 1; if (left < 0) left = 0; if (left > K - 1) left = K - 1;
    int right = lo;    if (right > K - 1) right = K - 1;
    int dl = abs(i - keep[left]);
    int dr = abs(i - keep[right]);
    nn[i] = (dl <= dr) ? left : right;
}

// ---------------------------------------------------------------------------
// host-side layer driver
// ---------------------------------------------------------------------------
static void run_conv(const float* A, int CA, const int* mapA,
                     const float* B, int CB,
                     const int* nb, int R, int Cout, const float* W,
                     const float* g, const float* bta,
                     float* H, float* HP, float* PB, float* SS, int splits,
                     bool doApply) {
    dim3 grid(CDIV(R, 64), Cout / 64, splits);
    float* target = (splits == 1) ? H : HP;
    if (CB > 0)
        conv_kernel<16, true><<<grid, 256>>>(A, CA, mapA, B, CB, nb, R, Cout, W, target, splits);
    else if (CA <= 8)
        conv_kernel<8, false><<<grid, 256>>>(A, CA, nullptr, nullptr, 0, nb, R, Cout, W, target, splits);
    else
        conv_kernel<16, false><<<grid, 256>>>(A, CA, nullptr, nullptr, 0, nb, R, Cout, W, target, splits);
    long long n = (long long)R * Cout;
    if (splits > 1)
        reduce_split_kernel<<<(int)CDIV(n, 256), 256>>>(H, HP, n, splits);
    int nblk = CDIV(R, 256);
    bn_reduce_kernel<<<nblk, 256>>>(H, R, Cout, PB);
    bn_finalize_kernel<<<Cout, 256>>>(PB, nblk, Cout, R, g, bta, SS);
    if (doApply)
        bn_apply_kernel<<<(int)CDIV(n, 256), 256>>>(H, n, Cout - 1, SS);
}

extern "C" void kernel_launch(void* const* d_in, const int* in_sizes, int n_in,
                              void* d_out, int out_size) {
    const float* x    = (const float*)d_in[0];
    const int*   nb32 = (const int*)d_in[1];
    const float* W_e1 = (const float*)d_in[2];
    const float* g_e1 = (const float*)d_in[3];
    const float* b_e1 = (const float*)d_in[4];
    const float* W_e2 = (const float*)d_in[5];
    const float* g_e2 = (const float*)d_in[6];
    const float* b_e2 = (const float*)d_in[7];
    const float* W_e3 = (const float*)d_in[8];
    const float* g_e3 = (const float*)d_in[9];
    const float* b_e3 = (const float*)d_in[10];
    const float* W_e4 = (const float*)d_in[11];
    const float* g_e4 = (const float*)d_in[12];
    const float* b_e4 = (const float*)d_in[13];
    const float* W_d3 = (const float*)d_in[14];
    const float* g_d3 = (const float*)d_in[15];
    const float* b_d3 = (const float*)d_in[16];
    const float* W_d2 = (const float*)d_in[17];
    const float* g_d2 = (const float*)d_in[18];
    const float* b_d2 = (const float*)d_in[19];
    const float* W_d1 = (const float*)d_in[20];
    const float* g_d1 = (const float*)d_in[21];
    const float* b_d1 = (const float*)d_in[22];
    const float* W_h  = (const float*)d_in[23];
    const float* b_h  = (const float*)d_in[24];
    float* out = (float*)d_out;

    float* gf = nullptr; cudaGetSymbolAddress((void**)&gf, g_f);
    int*   gi = nullptr; cudaGetSymbolAddress((void**)&gi, g_i);

    float* E1   = gf + F_E1;
    float* D1   = gf + F_D1;
    float* SC   = gf + F_SC;
    float* E1P  = gf + F_E1P;
    float* E2   = gf + F_E2;
    float* E2P  = gf + F_E2P;
    float* E3   = gf + F_E3;
    float* E3P  = gf + F_E3P;
    float* E4   = gf + F_E4;
    float* D3   = gf + F_D3;
    float* D2   = gf + F_D2;
    float* HP   = gf + F_HP;
    float* PB   = gf + F_PB;
    float* SS   = gf + F_SS;

    int* NB0  = gi + I_NB0;
    int* NB1  = gi + I_NB1;
    int* NB2  = gi + I_NB2;
    int* NB3  = gi + I_NB3;
    int* K1   = gi + I_K1;
    int* K2   = gi + I_K2;
    int* K3   = gi + I_K3;
    int* RM1  = gi + I_RM1;
    int* NN1  = gi + I_NN1;
    int* NN2  = gi + I_NN2;
    int* NN3  = gi + I_NN3;
    int* FEQ  = gi + I_FEQ;
    int* EQR  = gi + I_EQR;
    int* FKP  = gi + I_FKP;
    int* POS  = gi + I_POS;
    int* BSUM = gi + I_BSUM;
    unsigned* H1 = (unsigned*)(gi + I_H1);
    unsigned* H2 = (unsigned*)(gi + I_H2);
    int* SEL  = gi + I_SEL;

    const int nscanblk = CDIV(EN, 1024);  // 196

    // 0. reset accumulated state
    zero_hists_kernel<<<CDIV(16384 + 262144, 256), 256>>>(H1, H2);
    // 1. nb -> clipped int32 (input IS int32: jax x64 disabled)
    nbconv_kernel<<<CDIV(EN * 4, 256), 256>>>(nb32, EN * 4, EN, NB0);
    // 2. e1 = conv(x, nb0); BN apply fused with pool score
    run_conv(x, 5, nullptr, nullptr, 0, NB0, EN, 64, W_e1, g_e1, b_e1,
             E1, HP, PB, SS, 1, false);
    bn_apply_score_kernel<<<CDIV(EN, 256), 256>>>(E1, EN, SS, SC);
    // 3. pool1: exact top-1500 by row norm
    hist1_kernel<<<782, 256>>>(SC, EN, H1);
    pick1_kernel<<<1, 1024>>>(H1, T1, SEL);
    hist2_kernel<<<782, 256>>>(SC, EN, H2, SEL);
    pick2_kernel<<<1, 1024>>>(H2, T1, SEL);
    flags_eq_kernel<<<CDIV(EN, 256), 256>>>(SC, EN, SEL, FEQ);
    scan_blk_kernel<<<nscanblk, 256>>>(FEQ, EQR, BSUM, EN);
    scan_top_kernel<<<1, 1024>>>(BSUM, nscanblk);
    scan_add_kernel<<<CDIV(EN, 256), 256>>>(EQR, BSUM, EN);
    flags_keep_kernel<<<CDIV(EN, 256), 256>>>(SC, EN, SEL, EQR, FKP);
    scan_blk_kernel<<<nscanblk, 256>>>(FKP, POS, BSUM, EN);
    scan_top_kernel<<<1, 1024>>>(BSUM, nscanblk);
    scan_add_kernel<<<CDIV(EN, 256), 256>>>(POS, BSUM, EN);
    scatter_kernel<<<CDIV(EN, 256), 256>>>(FKP, POS, EN, K1, RM1);
    gather_pool1_kernel<<<CDIV(T1 * 64, 256), 256>>>(E1, NB0, K1, RM1, T1, 64, E1P, NB1);
    // 4. e2 / pool2
    run_conv(E1P, 64, nullptr, nullptr, 0, NB1, T1, 128, W_e2, g_e2, b_e2,
             E2, HP, PB, SS, 6, true);
    pool_small_kernel<<<1, 1024>>>(E2, NB1, T1, 128, T2, E2P, NB2, K2);
    // 5. e3 / pool3
    run_conv(E2P, 128, nullptr, nullptr, 0, NB2, T2, 256, W_e3, g_e3, b_e3,
             E3, HP, PB, SS, 6, true);
    pool_small_kernel<<<1, 1024>>>(E3, NB2, T2, 256, T3, E3P, NB3, K3);
    // 6. e4
    run_conv(E3P, 256, nullptr, nullptr, 0, NB3, T3, 512, W_e4, g_e4, b_e4,
             E4, HP, PB, SS, 8, true);
    // 7. d3 = scalar conv(virtual concat(unpool(e4), e3), nb2)
    nn_kernel<<<CDIV(T2, 256), 256>>>(K3, T3, T2, NN3);
    run_conv(E4, 512, NN3, E3, 256, NB2, T2, 256, W_d3, g_d3, b_d3,
             D3, HP, PB, SS, 12, true);
    // 8. d2 = scalar conv(virtual concat(unpool(d3), e2), nb1)
    nn_kernel<<<CDIV(T1, 256), 256>>>(K2, T2, T1, NN2);
    run_conv(D3, 256, NN2, E2, 128, NB1, T1, 128, W_d2, g_d2, b_d2,
             D2, HP, PB, SS, 8, true);
    // 9. d1 = TENSOR conv (split-TF32 mma, weight pre-cvt) over virtual concat
    nn_kernel<<<CDIV(EN, 256), 256>>>(K1, T1, EN, NN1);
    conv_d1_tensor_kernel<<<CDIV(EN, 128), 256>>>(D2, NN1, E1, NB0, EN, W_d1, D1);
    {   // BN stats for d1 (apply fused into head)
        int nblk = CDIV(EN, 256);
        bn_reduce_kernel<<<nblk, 256>>>(D1, EN, 64, PB);
        bn_finalize_kernel<<<64, 256>>>(PB, nblk, 64, EN, g_d1, b_d1, SS);
    }
    // 10. head (reads pre-BN d1, applies BN+ReLU inline)
    bn_apply_head_kernel<<<CDIV(EN, 256), 256>>>(D1, EN, SS, W_h, b_h, out);
}